// round 2
// baseline (speedup 1.0000x reference)
#include <cuda_runtime.h>
#include <math.h>

#define NBLK1 2048
#define LOG2E 1.44269504088896f

// scratch (static device allocations are allowed)
__device__ __align__(16) float g_ypre[4194304];   // (b,h,w,c) layout
__device__ float g_part[NBLK1 * 8];               // per-block group partials
__device__ float g_stats[32];                     // 16 x {mean, rsig}

// shared-memory float offsets
#define OFF_WIN   0        // [32][128]
#define OFF_WX    4096     // [64][36]
#define OFF_WOUT  6400     // [64][33]
#define OFF_WDT   8512     // [2][64]
#define OFF_BDT2  8640     // [64]
#define OFF_DS2   8704     // [64]
#define OFF_A2    8768     // [64][17]
#define OFF_XF    9856     // [64][33]
#define OFF_XP    11968    // [64][67]
#define OFF_GZ    16256    // [64][67]
#define OFF_DELTA 20544    // [64][67]
#define OFF_YS    24832    // [64][67]
#define OFF_B     29120    // [64][17]
#define OFF_C     30208    // [64][17]
#define OFF_DTSR  31296    // [64][2]
#define OFF_GACC  31424    // [8][4][2]
#define SMEM_FLOATS 31488

__device__ __forceinline__ float ex2f(float x) {
    float y; asm("ex2.approx.ftz.f32 %0, %1;" : "=f"(y) : "f"(x)); return y;
}

__global__ __launch_bounds__(256, 1) void k1_main(
    const float* __restrict__ x, const float* __restrict__ W_in,
    const float* __restrict__ W_x, const float* __restrict__ W_dt,
    const float* __restrict__ b_dt, const float* __restrict__ A_logs,
    const float* __restrict__ Ds, const float* __restrict__ W_out)
{
    extern __shared__ float S[];
    const int tid = threadIdx.x;
    const int bid = blockIdx.x;

    // ---------------- load weights to smem ----------------
    for (int i = tid; i < 4096; i += 256) S[OFF_WIN + i] = W_in[i];
    for (int i = tid; i < 64 * 34; i += 256) {
        int d = i / 34, j = i - d * 34;
        S[OFF_WX + d * 36 + j] = W_x[i];
    }
    for (int i = tid; i < 2048; i += 256) {
        int d = i >> 5, g = i & 31;
        S[OFF_WOUT + d * 33 + g] = W_out[i];
    }
    if (tid < 128) S[OFF_WDT + tid] = W_dt[tid];
    if (tid < 64) {
        S[OFF_BDT2 + tid] = 2.0f * b_dt[tid];
        S[OFF_DS2 + tid]  = 2.0f * Ds[tid];
    }
    for (int i = tid; i < 1024; i += 256) {
        int d = i >> 4, n = i & 15;
        S[OFF_A2 + d * 17 + n] = -__expf(A_logs[i]) * LOG2E;
    }

    // ---------------- load x tile (8 positions, same b,h; consecutive w) ----------------
    {
        int m0 = bid * 8;
        int b = m0 >> 12;
        int h = (m0 >> 6) & 63;
        int w0 = m0 & 63;
        const float* xb = x + b * (256 * 4096) + h * 64 + w0;
        for (int i = tid; i < 2048; i += 256) {
            int c = i >> 3, p = i & 7;     // c = channel 0..255, p = position 0..7
            int t = c >> 5, g = c & 31;
            S[OFF_XF + (p * 8 + t) * 33 + g] = xb[c * 4096 + p];
        }
    }
    __syncthreads();

    // ---------------- GEMM1: [64 rows x 32] @ [32 x 128] -> xp(0..63), gelu(z)(64..127)
    {
        int rp = tid >> 3;      // 0..31 -> rows {2rp, 2rp+1}
        int cg = tid & 7;       // 0..7  -> cols [16cg, 16cg+16)
        float acc[2][16];
        #pragma unroll
        for (int i = 0; i < 2; i++)
            #pragma unroll
            for (int j = 0; j < 16; j++) acc[i][j] = 0.0f;
        const float4* W4 = reinterpret_cast<const float4*>(&S[OFF_WIN]);
        #pragma unroll 4
        for (int k = 0; k < 32; k++) {
            float a0 = S[OFF_XF + (2 * rp) * 33 + k];
            float a1 = S[OFF_XF + (2 * rp + 1) * 33 + k];
            #pragma unroll
            for (int q = 0; q < 4; q++) {
                float4 w = W4[k * 32 + cg * 4 + q];
                acc[0][4*q+0] = fmaf(a0, w.x, acc[0][4*q+0]);
                acc[0][4*q+1] = fmaf(a0, w.y, acc[0][4*q+1]);
                acc[0][4*q+2] = fmaf(a0, w.z, acc[0][4*q+2]);
                acc[0][4*q+3] = fmaf(a0, w.w, acc[0][4*q+3]);
                acc[1][4*q+0] = fmaf(a1, w.x, acc[1][4*q+0]);
                acc[1][4*q+1] = fmaf(a1, w.y, acc[1][4*q+1]);
                acc[1][4*q+2] = fmaf(a1, w.z, acc[1][4*q+2]);
                acc[1][4*q+3] = fmaf(a1, w.w, acc[1][4*q+3]);
            }
        }
        #pragma unroll
        for (int i = 0; i < 2; i++) {
            int row = 2 * rp + i;
            #pragma unroll
            for (int j = 0; j < 16; j++) {
                int col = cg * 16 + j;
                float v = acc[i][j];
                if (col < 64) {
                    S[OFF_XP + row * 67 + col] = v;
                } else {
                    // exact gelu
                    float ge = 0.5f * v * (1.0f + erff(v * 0.70710678118f));
                    S[OFF_GZ + row * 67 + (col - 64)] = ge;
                }
            }
        }
    }
    __syncthreads();

    // ---------------- GEMM2: [64 x 64] @ [64 x 34] -> dts_raw(0..1), B(2..17), C(18..33)
    if (tid < 128) {
        int rq = tid >> 3;  // 0..15 -> rows 4rq..
        int cq = tid & 7;   // 0..7  -> cols 4cq.. (0..31)
        float acc[4][4];
        #pragma unroll
        for (int i = 0; i < 4; i++)
            #pragma unroll
            for (int j = 0; j < 4; j++) acc[i][j] = 0.0f;
        #pragma unroll 4
        for (int k = 0; k < 64; k++) {
            float a0 = S[OFF_XP + (4 * rq + 0) * 67 + k];
            float a1 = S[OFF_XP + (4 * rq + 1) * 67 + k];
            float a2 = S[OFF_XP + (4 * rq + 2) * 67 + k];
            float a3 = S[OFF_XP + (4 * rq + 3) * 67 + k];
            float w0 = S[OFF_WX + k * 36 + 4 * cq + 0];
            float w1 = S[OFF_WX + k * 36 + 4 * cq + 1];
            float w2 = S[OFF_WX + k * 36 + 4 * cq + 2];
            float w3 = S[OFF_WX + k * 36 + 4 * cq + 3];
            acc[0][0]=fmaf(a0,w0,acc[0][0]); acc[0][1]=fmaf(a0,w1,acc[0][1]); acc[0][2]=fmaf(a0,w2,acc[0][2]); acc[0][3]=fmaf(a0,w3,acc[0][3]);
            acc[1][0]=fmaf(a1,w0,acc[1][0]); acc[1][1]=fmaf(a1,w1,acc[1][1]); acc[1][2]=fmaf(a1,w2,acc[1][2]); acc[1][3]=fmaf(a1,w3,acc[1][3]);
            acc[2][0]=fmaf(a2,w0,acc[2][0]); acc[2][1]=fmaf(a2,w1,acc[2][1]); acc[2][2]=fmaf(a2,w2,acc[2][2]); acc[2][3]=fmaf(a2,w3,acc[2][3]);
            acc[3][0]=fmaf(a3,w0,acc[3][0]); acc[3][1]=fmaf(a3,w1,acc[3][1]); acc[3][2]=fmaf(a3,w2,acc[3][2]); acc[3][3]=fmaf(a3,w3,acc[3][3]);
        }
        #pragma unroll
        for (int i = 0; i < 4; i++) {
            int r = 4 * rq + i;
            #pragma unroll
            for (int j = 0; j < 4; j++) {
                int col = 4 * cq + j;
                float v = acc[i][j];
                if (col < 2)       S[OFF_DTSR + r * 2 + col] = v;
                else if (col < 18) S[OFF_B + r * 17 + (col - 2)] = v;
                else               S[OFF_C + r * 17 + (col - 18)] = v;
            }
        }
    } else {
        // cols 32,33 (-> C[14], C[15])
        int idx = tid - 128;
        int r = idx >> 1;
        int j = 32 + (idx & 1);
        float acc = 0.0f;
        #pragma unroll 8
        for (int k = 0; k < 64; k++)
            acc = fmaf(S[OFF_XP + r * 67 + k], S[OFF_WX + k * 36 + j], acc);
        S[OFF_C + r * 17 + (j - 18)] = acc;
    }
    __syncthreads();

    // ---------------- delta = softplus(dts_raw @ W_dt + 2*b_dt) ----------------
    for (int i = tid; i < 4096; i += 256) {
        int r = i >> 6, d = i & 63;
        float v = fmaf(S[OFF_DTSR + r * 2], S[OFF_WDT + d],
                  fmaf(S[OFF_DTSR + r * 2 + 1], S[OFF_WDT + 64 + d], S[OFF_BDT2 + d]));
        float sp = (v > 15.0f) ? v : log1pf(__expf(v));
        S[OFF_DELTA + r * 67 + d] = sp;
    }
    __syncthreads();

    // ---------------- bidirectional selective scan ----------------
    {
        int p  = tid >> 5;   // position 0..7
        int d0 = tid & 31;   // lanes d0 and d0+32
        const float* A2a = &S[OFF_A2 + d0 * 17];
        const float* A2b = &S[OFF_A2 + (d0 + 32) * 17];
        float h0[16], h1[16];
        #pragma unroll
        for (int n = 0; n < 16; n++) { h0[n] = 0.0f; h1[n] = 0.0f; }

        // forward
        for (int t = 0; t < 8; t++) {
            int r = p * 8 + t;
            float dl0 = S[OFF_DELTA + r * 67 + d0];
            float dl1 = S[OFF_DELTA + r * 67 + d0 + 32];
            float u0  = S[OFF_XP + r * 67 + d0];
            float u1  = S[OFF_XP + r * 67 + d0 + 32];
            float du0 = dl0 * u0, du1 = dl1 * u1;
            float y0 = 0.0f, y1 = 0.0f;
            #pragma unroll
            for (int n = 0; n < 16; n++) {
                float Bn = S[OFF_B + r * 17 + n];
                float Cn = S[OFF_C + r * 17 + n];
                float a0 = ex2f(dl0 * A2a[n]);
                float a1 = ex2f(dl1 * A2b[n]);
                h0[n] = fmaf(a0, h0[n], du0 * Bn);
                h1[n] = fmaf(a1, h1[n], du1 * Bn);
                y0 = fmaf(h0[n], Cn, y0);
                y1 = fmaf(h1[n], Cn, y1);
            }
            S[OFF_YS + r * 67 + d0]      = fmaf(u0, S[OFF_DS2 + d0], y0);
            S[OFF_YS + r * 67 + d0 + 32] = fmaf(u1, S[OFF_DS2 + d0 + 32], y1);
        }

        // backward (same projections, reversed token order), then gate with gelu(z)
        #pragma unroll
        for (int n = 0; n < 16; n++) { h0[n] = 0.0f; h1[n] = 0.0f; }
        for (int t = 7; t >= 0; t--) {
            int r = p * 8 + t;
            float dl0 = S[OFF_DELTA + r * 67 + d0];
            float dl1 = S[OFF_DELTA + r * 67 + d0 + 32];
            float u0  = S[OFF_XP + r * 67 + d0];
            float u1  = S[OFF_XP + r * 67 + d0 + 32];
            float du0 = dl0 * u0, du1 = dl1 * u1;
            float y0 = 0.0f, y1 = 0.0f;
            #pragma unroll
            for (int n = 0; n < 16; n++) {
                float Bn = S[OFF_B + r * 17 + n];
                float Cn = S[OFF_C + r * 17 + n];
                float a0 = ex2f(dl0 * A2a[n]);
                float a1 = ex2f(dl1 * A2b[n]);
                h0[n] = fmaf(a0, h0[n], du0 * Bn);
                h1[n] = fmaf(a1, h1[n], du1 * Bn);
                y0 = fmaf(h0[n], Cn, y0);
                y1 = fmaf(h1[n], Cn, y1);
            }
            S[OFF_YS + r * 67 + d0]      = (S[OFF_YS + r * 67 + d0]      + y0) * S[OFF_GZ + r * 67 + d0];
            S[OFF_YS + r * 67 + d0 + 32] = (S[OFF_YS + r * 67 + d0 + 32] + y1) * S[OFF_GZ + r * 67 + d0 + 32];
        }
    }
    __syncthreads();

    // ---------------- GEMM3: [64 x 64] @ [64 x 32] -> y_pre + group partials ----------------
    {
        int rp = tid >> 3;   // 0..31 -> rows {2rp, 2rp+1}
        int cq = tid & 7;    // 0..7  -> cols 4cq..
        float acc[2][4];
        #pragma unroll
        for (int i = 0; i < 2; i++)
            #pragma unroll
            for (int j = 0; j < 4; j++) acc[i][j] = 0.0f;
        #pragma unroll 4
        for (int k = 0; k < 64; k++) {
            float a0 = S[OFF_YS + (2 * rp) * 67 + k];
            float a1 = S[OFF_YS + (2 * rp + 1) * 67 + k];
            float w0 = S[OFF_WOUT + k * 33 + 4 * cq + 0];
            float w1 = S[OFF_WOUT + k * 33 + 4 * cq + 1];
            float w2 = S[OFF_WOUT + k * 33 + 4 * cq + 2];
            float w3 = S[OFF_WOUT + k * 33 + 4 * cq + 3];
            acc[0][0]=fmaf(a0,w0,acc[0][0]); acc[0][1]=fmaf(a0,w1,acc[0][1]);
            acc[0][2]=fmaf(a0,w2,acc[0][2]); acc[0][3]=fmaf(a0,w3,acc[0][3]);
            acc[1][0]=fmaf(a1,w0,acc[1][0]); acc[1][1]=fmaf(a1,w1,acc[1][1]);
            acc[1][2]=fmaf(a1,w2,acc[1][2]); acc[1][3]=fmaf(a1,w3,acc[1][3]);
        }
        int m0 = bid * 8;
        float s = 0.0f, ss = 0.0f;
        #pragma unroll
        for (int i = 0; i < 2; i++) {
            int row = 2 * rp + i;
            int p = row >> 3, t = row & 7;
            float4 v4 = make_float4(acc[i][0], acc[i][1], acc[i][2], acc[i][3]);
            *reinterpret_cast<float4*>(&g_ypre[(m0 + p) * 256 + t * 32 + 4 * cq]) = v4;
            s  += acc[i][0] + acc[i][1] + acc[i][2] + acc[i][3];
            ss += acc[i][0]*acc[i][0] + acc[i][1]*acc[i][1] + acc[i][2]*acc[i][2] + acc[i][3]*acc[i][3];
        }
        // all 8 outputs of this thread belong to group (rp & 3); segmented reduce over 8 lanes
        #pragma unroll
        for (int off = 4; off; off >>= 1) {
            s  += __shfl_down_sync(0xffffffffu, s,  off, 8);
            ss += __shfl_down_sync(0xffffffffu, ss, off, 8);
        }
        if ((tid & 7) == 0) {
            int w = tid >> 5, g = rp & 3;
            S[OFF_GACC + (w * 4 + g) * 2]     = s;
            S[OFF_GACC + (w * 4 + g) * 2 + 1] = ss;
        }
    }
    __syncthreads();
    if (tid < 8) {
        int g = tid & 3, hh = tid >> 2;
        float v = 0.0f;
        #pragma unroll
        for (int w = 0; w < 8; w++) v += S[OFF_GACC + (w * 4 + g) * 2 + hh];
        g_part[bid * 8 + g * 2 + hh] = v;
    }
}

// ---------------- kernel 2: reduce partials -> 16 (b,group) stats ----------------
__global__ void k2_stats() {
    __shared__ float ssum[256], ssq[256];
    int b = blockIdx.x >> 2, g = blockIdx.x & 3;
    int tid = threadIdx.x;
    float s = 0.0f, q = 0.0f;
    for (int j = tid; j < 512; j += 256) {
        int blk = b * 512 + j;
        s += g_part[blk * 8 + g * 2];
        q += g_part[blk * 8 + g * 2 + 1];
    }
    ssum[tid] = s; ssq[tid] = q;
    __syncthreads();
    for (int st = 128; st; st >>= 1) {
        if (tid < st) { ssum[tid] += ssum[tid + st]; ssq[tid] += ssq[tid + st]; }
        __syncthreads();
    }
    if (tid == 0) {
        float invN = 1.0f / 262144.0f;
        float mean = ssum[0] * invN;
        float var  = ssq[0] * invN - mean * mean;
        g_stats[blockIdx.x * 2]     = mean;
        g_stats[blockIdx.x * 2 + 1] = rsqrtf(var + 1e-5f);
    }
}

// ---------------- kernel 3: groupnorm affine + transpose + residual ----------------
__global__ __launch_bounds__(256) void k3_final(
    const float* __restrict__ x, const float* __restrict__ gn_w,
    const float* __restrict__ gn_b, float* __restrict__ out)
{
    __shared__ float sm[32][33];
    int tx = threadIdx.x, ty = threadIdx.y;
    int ct = blockIdx.x & 7, wt = blockIdx.x >> 3;
    int h = blockIdx.y, b = blockIdx.z;
    int c0 = ct * 32, w0 = wt * 32;
    int c = c0 + tx;
    int grp = c >> 6;
    float mean = g_stats[(b * 4 + grp) * 2];
    float rsig = g_stats[(b * 4 + grp) * 2 + 1];
    float gw = gn_w[c], gb = gn_b[c];
    const float* yp = g_ypre + ((b * 64 + h) * 64 + w0) * 256;
    #pragma unroll
    for (int i = 0; i < 4; i++) {
        int wl = ty + 8 * i;
        float v = yp[wl * 256 + c];
        sm[wl][tx] = fmaf((v - mean) * rsig, gw, gb);
    }
    __syncthreads();
    #pragma unroll
    for (int i = 0; i < 4; i++) {
        int cl = ty + 8 * i;
        int gi = ((b * 256 + c0 + cl) * 64 + h) * 64 + w0 + tx;
        out[gi] = x[gi] + sm[tx][cl];
    }
}

extern "C" void kernel_launch(void* const* d_in, const int* in_sizes, int n_in,
                              void* d_out, int out_size) {
    const float* x      = (const float*)d_in[0];
    const float* W_in   = (const float*)d_in[1];
    const float* W_x    = (const float*)d_in[2];
    const float* W_dt   = (const float*)d_in[3];
    const float* b_dt   = (const float*)d_in[4];
    const float* A_logs = (const float*)d_in[5];
    const float* Ds     = (const float*)d_in[6];
    const float* W_out  = (const float*)d_in[7];
    const float* gn_w   = (const float*)d_in[8];
    const float* gn_b   = (const float*)d_in[9];
    float* out = (float*)d_out;

    cudaFuncSetAttribute(k1_main, cudaFuncAttributeMaxDynamicSharedMemorySize,
                         SMEM_FLOATS * 4);
    k1_main<<<NBLK1, 256, SMEM_FLOATS * 4>>>(x, W_in, W_x, W_dt, b_dt, A_logs, Ds, W_out);
    k2_stats<<<16, 256>>>();
    k3_final<<<dim3(16, 64, 4), dim3(32, 8)>>>(x, gn_w, gn_b, out);
}

// round 3
// speedup vs baseline: 1.2318x; 1.2318x over previous
#include <cuda_runtime.h>
#include <math.h>

#define NBLK1 2048
#define LOG2E 1.44269504088896f

__device__ __align__(16) float g_ypre[4194304];   // (b,h,w,c) layout
__device__ float g_part[NBLK1 * 8];
__device__ float g_stats[32];

// shared-memory float offsets
#define OFF_WIN   0        // [32][128]
#define OFF_WX    4096     // [64][36]
#define OFF_WOUT  6400     // [64][33]
#define OFF_WDT   8512     // [2][64]
#define OFF_BDT2  8640     // [64]
#define OFF_DS2   8704     // [64]
#define OFF_A2    8768     // [64][17]
#define OFF_XF    9856     // [64][33]
#define OFF_XP    11968    // [64][67]
#define OFF_GZ    16256    // [64][67]
#define OFF_YS    20544    // [64][67]
#define OFF_B     24832    // [64][17]
#define OFF_C     25920    // [64][17]
#define OFF_DTSR  27008    // [64][2]
#define OFF_GACC  27136    // [8][4][2]
#define SMEM_FLOATS 27204  // 108816 bytes -> 2 CTAs/SM

__device__ __forceinline__ float ex2f(float x) {
    float y; asm("ex2.approx.ftz.f32 %0, %1;" : "=f"(y) : "f"(x)); return y;
}

__global__ __launch_bounds__(256, 2) void k1_main(
    const float* __restrict__ x, const float* __restrict__ W_in,
    const float* __restrict__ W_x, const float* __restrict__ W_dt,
    const float* __restrict__ b_dt, const float* __restrict__ A_logs,
    const float* __restrict__ Ds, const float* __restrict__ W_out)
{
    extern __shared__ float S[];
    const int tid = threadIdx.x;
    const int bid = blockIdx.x;

    // ---------------- load weights to smem ----------------
    for (int i = tid; i < 4096; i += 256) S[OFF_WIN + i] = W_in[i];
    for (int i = tid; i < 64 * 34; i += 256) {
        int d = i / 34, j = i - d * 34;
        S[OFF_WX + d * 36 + j] = W_x[i];
    }
    for (int i = tid; i < 2048; i += 256) {
        int d = i >> 5, g = i & 31;
        S[OFF_WOUT + d * 33 + g] = W_out[i];
    }
    if (tid < 128) S[OFF_WDT + tid] = W_dt[tid];
    if (tid < 64) {
        S[OFF_BDT2 + tid] = 2.0f * b_dt[tid];
        S[OFF_DS2 + tid]  = 2.0f * Ds[tid];
    }
    int ok = 1;
    for (int i = tid; i < 1024; i += 256) {
        int d = i >> 4, n = i & 15;
        float ae = __expf(A_logs[i]);
        if (fabsf(ae - (float)(n + 1)) > 1e-3f * (float)(n + 1)) ok = 0;
        S[OFF_A2 + d * 17 + n] = -ae * LOG2E;
    }

    // ---------------- load x tile (8 positions, same b,h; consecutive w) ----------------
    {
        int m0 = bid * 8;
        int b = m0 >> 12;
        int h = (m0 >> 6) & 63;
        int w0 = m0 & 63;
        const float* xb = x + b * (256 * 4096) + h * 64 + w0;
        for (int i = tid; i < 2048; i += 256) {
            int c = i >> 3, p = i & 7;
            int t = c >> 5, g = c & 31;
            S[OFF_XF + (p * 8 + t) * 33 + g] = xb[c * 4096 + p];
        }
    }
    const int fast = __syncthreads_and(ok);

    // ---------------- GEMM1: [64 x 32] @ [32 x 128] -> xp(0..63), gelu(z)(64..127)
    {
        int rp = tid >> 3;
        int cg = tid & 7;
        float acc[2][16];
        #pragma unroll
        for (int i = 0; i < 2; i++)
            #pragma unroll
            for (int j = 0; j < 16; j++) acc[i][j] = 0.0f;
        const float4* W4 = reinterpret_cast<const float4*>(&S[OFF_WIN]);
        #pragma unroll 4
        for (int k = 0; k < 32; k++) {
            float a0 = S[OFF_XF + (2 * rp) * 33 + k];
            float a1 = S[OFF_XF + (2 * rp + 1) * 33 + k];
            #pragma unroll
            for (int q = 0; q < 4; q++) {
                float4 w = W4[k * 32 + cg * 4 + q];
                acc[0][4*q+0] = fmaf(a0, w.x, acc[0][4*q+0]);
                acc[0][4*q+1] = fmaf(a0, w.y, acc[0][4*q+1]);
                acc[0][4*q+2] = fmaf(a0, w.z, acc[0][4*q+2]);
                acc[0][4*q+3] = fmaf(a0, w.w, acc[0][4*q+3]);
                acc[1][4*q+0] = fmaf(a1, w.x, acc[1][4*q+0]);
                acc[1][4*q+1] = fmaf(a1, w.y, acc[1][4*q+1]);
                acc[1][4*q+2] = fmaf(a1, w.z, acc[1][4*q+2]);
                acc[1][4*q+3] = fmaf(a1, w.w, acc[1][4*q+3]);
            }
        }
        #pragma unroll
        for (int i = 0; i < 2; i++) {
            int row = 2 * rp + i;
            #pragma unroll
            for (int j = 0; j < 16; j++) {
                int col = cg * 16 + j;
                float v = acc[i][j];
                if (col < 64) {
                    S[OFF_XP + row * 67 + col] = v;
                } else {
                    float ge = 0.5f * v * (1.0f + erff(v * 0.70710678118f));
                    S[OFF_GZ + row * 67 + (col - 64)] = ge;
                }
            }
        }
    }
    __syncthreads();

    // ---------------- GEMM2: [64 x 64] @ [64 x 34] -> dts_raw(0..1), B(2..17), C(18..33)
    if (tid < 128) {
        int rq = tid >> 3;
        int cq = tid & 7;
        float acc[4][4];
        #pragma unroll
        for (int i = 0; i < 4; i++)
            #pragma unroll
            for (int j = 0; j < 4; j++) acc[i][j] = 0.0f;
        #pragma unroll 4
        for (int k = 0; k < 64; k++) {
            float a0 = S[OFF_XP + (4 * rq + 0) * 67 + k];
            float a1 = S[OFF_XP + (4 * rq + 1) * 67 + k];
            float a2 = S[OFF_XP + (4 * rq + 2) * 67 + k];
            float a3 = S[OFF_XP + (4 * rq + 3) * 67 + k];
            float w0 = S[OFF_WX + k * 36 + 4 * cq + 0];
            float w1 = S[OFF_WX + k * 36 + 4 * cq + 1];
            float w2 = S[OFF_WX + k * 36 + 4 * cq + 2];
            float w3 = S[OFF_WX + k * 36 + 4 * cq + 3];
            acc[0][0]=fmaf(a0,w0,acc[0][0]); acc[0][1]=fmaf(a0,w1,acc[0][1]); acc[0][2]=fmaf(a0,w2,acc[0][2]); acc[0][3]=fmaf(a0,w3,acc[0][3]);
            acc[1][0]=fmaf(a1,w0,acc[1][0]); acc[1][1]=fmaf(a1,w1,acc[1][1]); acc[1][2]=fmaf(a1,w2,acc[1][2]); acc[1][3]=fmaf(a1,w3,acc[1][3]);
            acc[2][0]=fmaf(a2,w0,acc[2][0]); acc[2][1]=fmaf(a2,w1,acc[2][1]); acc[2][2]=fmaf(a2,w2,acc[2][2]); acc[2][3]=fmaf(a2,w3,acc[2][3]);
            acc[3][0]=fmaf(a3,w0,acc[3][0]); acc[3][1]=fmaf(a3,w1,acc[3][1]); acc[3][2]=fmaf(a3,w2,acc[3][2]); acc[3][3]=fmaf(a3,w3,acc[3][3]);
        }
        #pragma unroll
        for (int i = 0; i < 4; i++) {
            int r = 4 * rq + i;
            #pragma unroll
            for (int j = 0; j < 4; j++) {
                int col = 4 * cq + j;
                float v = acc[i][j];
                if (col < 2)       S[OFF_DTSR + r * 2 + col] = v;
                else if (col < 18) S[OFF_B + r * 17 + (col - 2)] = v;
                else               S[OFF_C + r * 17 + (col - 18)] = v;
            }
        }
    } else {
        int idx = tid - 128;
        int r = idx >> 1;
        int j = 32 + (idx & 1);
        float acc = 0.0f;
        #pragma unroll 8
        for (int k = 0; k < 64; k++)
            acc = fmaf(S[OFF_XP + r * 67 + k], S[OFF_WX + k * 36 + j], acc);
        S[OFF_C + r * 17 + (j - 18)] = acc;
    }
    __syncthreads();

    // ---------------- bidirectional selective scan (delta fused, register-resident) ----
    {
        const int p  = tid >> 5;
        const int d0 = tid & 31;
        float du0[8], du1[8], dl0[8], dl1[8], rr0[8], rr1[8];
        #pragma unroll
        for (int t = 0; t < 8; t++) {
            int r = p * 8 + t;
            float q0 = S[OFF_DTSR + r * 2];
            float q1 = S[OFF_DTSR + r * 2 + 1];
            float v0 = fmaf(q0, S[OFF_WDT + d0],      fmaf(q1, S[OFF_WDT + 64 + d0],      S[OFF_BDT2 + d0]));
            float v1 = fmaf(q0, S[OFF_WDT + d0 + 32], fmaf(q1, S[OFF_WDT + 96 + d0],      S[OFF_BDT2 + d0 + 32]));
            float e0 = __expf(v0), e1 = __expf(v1);
            // softplus: series for v<-3 (|err|<2e-6), exact path otherwise
            float s0 = (v0 < -3.0f) ? e0 * (1.0f - e0 * (0.5f - 0.33333334f * e0)) : log1pf(e0);
            float s1 = (v1 < -3.0f) ? e1 * (1.0f - e1 * (0.5f - 0.33333334f * e1)) : log1pf(e1);
            dl0[t] = s0; dl1[t] = s1;
            du0[t] = s0 * S[OFF_XP + r * 67 + d0];
            du1[t] = s1 * S[OFF_XP + r * 67 + d0 + 32];
            rr0[t] = ex2f(-s0 * LOG2E);   // exp(-delta)
            rr1[t] = ex2f(-s1 * LOG2E);
        }
        const float* A2a = &S[OFF_A2 + d0 * 17];
        const float* A2b = &S[OFF_A2 + (d0 + 32) * 17];
        float h0[16], h1[16];
        #pragma unroll
        for (int n = 0; n < 16; n++) { h0[n] = 0.0f; h1[n] = 0.0f; }

        // forward pass
        for (int t = 0; t < 8; t++) {
            int r = p * 8 + t;
            float y0 = 0.0f, y1 = 0.0f;
            if (fast) {
                float a0 = rr0[t], a1 = rr1[t];
                #pragma unroll
                for (int n = 0; n < 16; n++) {
                    float Bn = S[OFF_B + r * 17 + n];
                    float Cn = S[OFF_C + r * 17 + n];
                    h0[n] = fmaf(a0, h0[n], du0[t] * Bn);
                    h1[n] = fmaf(a1, h1[n], du1[t] * Bn);
                    y0 = fmaf(h0[n], Cn, y0);
                    y1 = fmaf(h1[n], Cn, y1);
                    a0 *= rr0[t]; a1 *= rr1[t];
                }
            } else {
                #pragma unroll
                for (int n = 0; n < 16; n++) {
                    float Bn = S[OFF_B + r * 17 + n];
                    float Cn = S[OFF_C + r * 17 + n];
                    float a0 = ex2f(dl0[t] * A2a[n]);
                    float a1 = ex2f(dl1[t] * A2b[n]);
                    h0[n] = fmaf(a0, h0[n], du0[t] * Bn);
                    h1[n] = fmaf(a1, h1[n], du1[t] * Bn);
                    y0 = fmaf(h0[n], Cn, y0);
                    y1 = fmaf(h1[n], Cn, y1);
                }
            }
            float u0 = S[OFF_XP + r * 67 + d0];
            float u1 = S[OFF_XP + r * 67 + d0 + 32];
            S[OFF_YS + r * 67 + d0]      = fmaf(u0, S[OFF_DS2 + d0], y0);
            S[OFF_YS + r * 67 + d0 + 32] = fmaf(u1, S[OFF_DS2 + d0 + 32], y1);
        }

        // backward pass + gate
        #pragma unroll
        for (int n = 0; n < 16; n++) { h0[n] = 0.0f; h1[n] = 0.0f; }
        for (int t = 7; t >= 0; t--) {
            int r = p * 8 + t;
            float y0 = 0.0f, y1 = 0.0f;
            if (fast) {
                float a0 = rr0[t], a1 = rr1[t];
                #pragma unroll
                for (int n = 0; n < 16; n++) {
                    float Bn = S[OFF_B + r * 17 + n];
                    float Cn = S[OFF_C + r * 17 + n];
                    h0[n] = fmaf(a0, h0[n], du0[t] * Bn);
                    h1[n] = fmaf(a1, h1[n], du1[t] * Bn);
                    y0 = fmaf(h0[n], Cn, y0);
                    y1 = fmaf(h1[n], Cn, y1);
                    a0 *= rr0[t]; a1 *= rr1[t];
                }
            } else {
                #pragma unroll
                for (int n = 0; n < 16; n++) {
                    float Bn = S[OFF_B + r * 17 + n];
                    float Cn = S[OFF_C + r * 17 + n];
                    float a0 = ex2f(dl0[t] * A2a[n]);
                    float a1 = ex2f(dl1[t] * A2b[n]);
                    h0[n] = fmaf(a0, h0[n], du0[t] * Bn);
                    h1[n] = fmaf(a1, h1[n], du1[t] * Bn);
                    y0 = fmaf(h0[n], Cn, y0);
                    y1 = fmaf(h1[n], Cn, y1);
                }
            }
            S[OFF_YS + r * 67 + d0]      = (S[OFF_YS + r * 67 + d0]      + y0) * S[OFF_GZ + r * 67 + d0];
            S[OFF_YS + r * 67 + d0 + 32] = (S[OFF_YS + r * 67 + d0 + 32] + y1) * S[OFF_GZ + r * 67 + d0 + 32];
        }
    }
    __syncthreads();

    // ---------------- GEMM3: [64 x 64] @ [64 x 32] -> y_pre + group partials ----------------
    {
        int rp = tid >> 3;
        int cq = tid & 7;
        float acc[2][4];
        #pragma unroll
        for (int i = 0; i < 2; i++)
            #pragma unroll
            for (int j = 0; j < 4; j++) acc[i][j] = 0.0f;
        #pragma unroll 4
        for (int k = 0; k < 64; k++) {
            float a0 = S[OFF_YS + (2 * rp) * 67 + k];
            float a1 = S[OFF_YS + (2 * rp + 1) * 67 + k];
            float w0 = S[OFF_WOUT + k * 33 + 4 * cq + 0];
            float w1 = S[OFF_WOUT + k * 33 + 4 * cq + 1];
            float w2 = S[OFF_WOUT + k * 33 + 4 * cq + 2];
            float w3 = S[OFF_WOUT + k * 33 + 4 * cq + 3];
            acc[0][0]=fmaf(a0,w0,acc[0][0]); acc[0][1]=fmaf(a0,w1,acc[0][1]);
            acc[0][2]=fmaf(a0,w2,acc[0][2]); acc[0][3]=fmaf(a0,w3,acc[0][3]);
            acc[1][0]=fmaf(a1,w0,acc[1][0]); acc[1][1]=fmaf(a1,w1,acc[1][1]);
            acc[1][2]=fmaf(a1,w2,acc[1][2]); acc[1][3]=fmaf(a1,w3,acc[1][3]);
        }
        int m0 = bid * 8;
        float s = 0.0f, ss = 0.0f;
        #pragma unroll
        for (int i = 0; i < 2; i++) {
            int row = 2 * rp + i;
            int p = row >> 3, t = row & 7;
            float4 v4 = make_float4(acc[i][0], acc[i][1], acc[i][2], acc[i][3]);
            *reinterpret_cast<float4*>(&g_ypre[(m0 + p) * 256 + t * 32 + 4 * cq]) = v4;
            s  += acc[i][0] + acc[i][1] + acc[i][2] + acc[i][3];
            ss += acc[i][0]*acc[i][0] + acc[i][1]*acc[i][1] + acc[i][2]*acc[i][2] + acc[i][3]*acc[i][3];
        }
        #pragma unroll
        for (int off = 4; off; off >>= 1) {
            s  += __shfl_down_sync(0xffffffffu, s,  off, 8);
            ss += __shfl_down_sync(0xffffffffu, ss, off, 8);
        }
        if ((tid & 7) == 0) {
            int w = tid >> 5, g = rp & 3;
            S[OFF_GACC + (w * 4 + g) * 2]     = s;
            S[OFF_GACC + (w * 4 + g) * 2 + 1] = ss;
        }
    }
    __syncthreads();
    if (tid < 8) {
        int g = tid & 3, hh = tid >> 2;
        float v = 0.0f;
        #pragma unroll
        for (int w = 0; w < 8; w++) v += S[OFF_GACC + (w * 4 + g) * 2 + hh];
        g_part[bid * 8 + g * 2 + hh] = v;
    }
}

// ---------------- kernel 2: reduce partials -> 16 (b,group) stats ----------------
__global__ void k2_stats() {
    __shared__ float ssum[256], ssq[256];
    int b = blockIdx.x >> 2, g = blockIdx.x & 3;
    int tid = threadIdx.x;
    float s = 0.0f, q = 0.0f;
    for (int j = tid; j < 512; j += 256) {
        int blk = b * 512 + j;
        s += g_part[blk * 8 + g * 2];
        q += g_part[blk * 8 + g * 2 + 1];
    }
    ssum[tid] = s; ssq[tid] = q;
    __syncthreads();
    for (int st = 128; st; st >>= 1) {
        if (tid < st) { ssum[tid] += ssum[tid + st]; ssq[tid] += ssq[tid + st]; }
        __syncthreads();
    }
    if (tid == 0) {
        float invN = 1.0f / 262144.0f;
        float mean = ssum[0] * invN;
        float var  = ssq[0] * invN - mean * mean;
        g_stats[blockIdx.x * 2]     = mean;
        g_stats[blockIdx.x * 2 + 1] = rsqrtf(var + 1e-5f);
    }
}

// ---------------- kernel 3: groupnorm affine + transpose + residual ----------------
__global__ __launch_bounds__(256) void k3_final(
    const float* __restrict__ x, const float* __restrict__ gn_w,
    const float* __restrict__ gn_b, float* __restrict__ out)
{
    __shared__ float sm[32][33];
    int tx = threadIdx.x, ty = threadIdx.y;
    int ct = blockIdx.x & 7, wt = blockIdx.x >> 3;
    int h = blockIdx.y, b = blockIdx.z;
    int c0 = ct * 32, w0 = wt * 32;
    int c = c0 + tx;
    int grp = c >> 6;
    float mean = g_stats[(b * 4 + grp) * 2];
    float rsig = g_stats[(b * 4 + grp) * 2 + 1];
    float gw = gn_w[c], gb = gn_b[c];
    const float* yp = g_ypre + ((b * 64 + h) * 64 + w0) * 256;
    #pragma unroll
    for (int i = 0; i < 4; i++) {
        int wl = ty + 8 * i;
        float v = yp[wl * 256 + c];
        sm[wl][tx] = fmaf((v - mean) * rsig, gw, gb);
    }
    __syncthreads();
    #pragma unroll
    for (int i = 0; i < 4; i++) {
        int cl = ty + 8 * i;
        int gi = ((b * 256 + c0 + cl) * 64 + h) * 64 + w0 + tx;
        out[gi] = x[gi] + sm[tx][cl];
    }
}

extern "C" void kernel_launch(void* const* d_in, const int* in_sizes, int n_in,
                              void* d_out, int out_size) {
    const float* x      = (const float*)d_in[0];
    const float* W_in   = (const float*)d_in[1];
    const float* W_x    = (const float*)d_in[2];
    const float* W_dt   = (const float*)d_in[3];
    const float* b_dt   = (const float*)d_in[4];
    const float* A_logs = (const float*)d_in[5];
    const float* Ds     = (const float*)d_in[6];
    const float* W_out  = (const float*)d_in[7];
    const float* gn_w   = (const float*)d_in[8];
    const float* gn_b   = (const float*)d_in[9];
    float* out = (float*)d_out;

    cudaFuncSetAttribute(k1_main, cudaFuncAttributeMaxDynamicSharedMemorySize,
                         SMEM_FLOATS * 4);
    k1_main<<<NBLK1, 256, SMEM_FLOATS * 4>>>(x, W_in, W_x, W_dt, b_dt, A_logs, Ds, W_out);
    k2_stats<<<16, 256>>>();
    k3_final<<<dim3(16, 64, 4), dim3(32, 8)>>>(x, gn_w, gn_b, out);
}